// round 3
// baseline (speedup 1.0000x reference)
#include <cuda_runtime.h>
#include <math.h>

#define MAXN 10000
#define MAXE 160000

// ---------------- device scratch (module-load allocations are allowed) ------
__device__ float g_cst;                          // CST_SILU
__device__ float g_xs[MAXN * 288];               // up-projected node features
__device__ float g_mid[MAXN * 1120];             // per-node aggregated messages

// layout of g_xs per node (288):
//   [0:32)    l0:  w
//   [32:128)  l1:  w*3+i
//   [128:288) l2:  w*5+i
// layout of g_mid per node (1120):
//   [0:96)      l0 segs (paths 0,1,2): seg*32 + u
//   [96:480)    l1 segs (paths 3,4,5,6): 96 + seg*96 + u*3 + i
//   [480:1120)  l2 segs (paths 7,8,9,10): 480 + seg*160 + u*5 + k

__device__ __forceinline__ float silu_f(float v) { return v / (1.0f + expf(-v)); }

// ---------------- CST_SILU via composite Simpson (double) -------------------
__global__ void cst_kernel() {
    __shared__ double red[256];
    const int t = threadIdx.x;
    const int NI = 4096;                 // intervals (even)
    const double h = 24.0 / NI;          // over [-12, 12]
    double s = 0.0;
    for (int i = t; i <= NI; i += 256) {
        double xx = -12.0 + h * i;
        double sig = 1.0 / (1.0 + exp(-xx));
        double f = xx * sig;
        f = f * f * exp(-0.5 * xx * xx);
        double c = (i == 0 || i == NI) ? 1.0 : ((i & 1) ? 4.0 : 2.0);
        s += c * f;
    }
    red[t] = s;
    __syncthreads();
    for (int o = 128; o > 0; o >>= 1) {
        if (t < o) red[t] += red[t + o];
        __syncthreads();
    }
    if (t == 0) {
        double I = red[0] * h / 3.0 / 2.5066282746310005024;  // / sqrt(2*pi)
        g_cst = (float)(1.0 / sqrt(I));
    }
}

// ---------------- zero mid ---------------------------------------------------
__global__ void zero_kernel(int n4) {
    int i = blockIdx.x * blockDim.x + threadIdx.x;
    if (i < n4) reinterpret_cast<float4*>(g_mid)[i] = make_float4(0.f, 0.f, 0.f, 0.f);
}

// ---------------- node up-projection ----------------------------------------
__global__ void up_kernel(const float* __restrict__ f_in,
                          const float* __restrict__ Wu0,
                          const float* __restrict__ Wu1,
                          const float* __restrict__ Wu2) {
    const int n = blockIdx.x;
    const int t = threadIdx.x;  // 288 threads
    __shared__ float fs[288];
    fs[t] = f_in[n * 288 + t];
    __syncthreads();
    int i, off;
    int w;
    const float* W;
    int d;
    if (t < 32)       { w = t;        i = 0;          d = 1; off = 0;   W = Wu0; }
    else if (t < 128) { int c = t-32;  w = c / 3; i = c % 3; d = 3; off = 32;  W = Wu1; }
    else              { int c = t-128; w = c / 5; i = c % 5; d = 5; off = 128; W = Wu2; }
    float acc = 0.f;
#pragma unroll 8
    for (int u = 0; u < 32; u++)
        acc = fmaf(fs[off + u * d + i], __ldg(W + u * 32 + w), acc);
    g_xs[n * 288 + t] = acc * 0.17677669529663687f;  // 1/sqrt(32)
}

// ---------------- fused per-edge kernel (warp per edge) ---------------------
__global__ void __launch_bounds__(256) edge_kernel(
    const float* __restrict__ pos, const int* __restrict__ batch,
    const int* __restrict__ esrc, const int* __restrict__ edst,
    const float* __restrict__ shifts, const float* __restrict__ cell,
    const float* __restrict__ Wr0, const float* __restrict__ Wr1,
    const float* __restrict__ Wr2, const float* __restrict__ Wr3, int E)
{
    __shared__ float hb[8][2][64];
    __shared__ float ws[8][352];

    const int wid  = threadIdx.x >> 5;
    const int lane = threadIdx.x & 31;
    const int e = blockIdx.x * 8 + wid;
    if (e >= E) return;

    const int src = __ldg(esrc + e);
    const int dst = __ldg(edst + e);

    // ---- geometry (redundant across lanes; broadcast loads) ----
    const float sx = __ldg(shifts + 3*e), sy = __ldg(shifts + 3*e+1), sz = __ldg(shifts + 3*e+2);
    const float* Cc = cell + 9 * __ldg(batch + src);
    float vx = __ldg(pos+3*dst+0) - __ldg(pos+3*src+0) + sx*__ldg(Cc+0) + sy*__ldg(Cc+3) + sz*__ldg(Cc+6);
    float vy = __ldg(pos+3*dst+1) - __ldg(pos+3*src+1) + sx*__ldg(Cc+1) + sy*__ldg(Cc+4) + sz*__ldg(Cc+7);
    float vz = __ldg(pos+3*dst+2) - __ldg(pos+3*src+2) + sx*__ldg(Cc+2) + sy*__ldg(Cc+5) + sz*__ldg(Cc+8);
    float L = sqrtf(vx*vx + vy*vy + vz*vz);
    float inv = 1.0f / fmaxf(L, 1e-12f);
    float ux = vx*inv, uy = vy*inv, uz = vz*inv;

    const float cst = g_cst;

    // ---- radial embedding: step = 5/9 ----
    float emb[8];
#pragma unroll
    for (int k = 0; k < 8; k++) {
        float tt = (L - (float)(k + 1) * (5.0f / 9.0f)) * 1.8f;
        emb[k] = expf(-tt * tt) * 2.525381361380527f;  // sqrt(8)/1.12
    }

    const int o0 = 2 * lane;
    // ---- layer 1: 8 -> 64 ----
    {
        float a0 = 0.f, a1 = 0.f;
#pragma unroll
        for (int j = 0; j < 8; j++) {
            float2 wv = *reinterpret_cast<const float2*>(Wr0 + j * 64 + o0);
            a0 = fmaf(emb[j], wv.x, a0);
            a1 = fmaf(emb[j], wv.y, a1);
        }
        hb[wid][0][o0]     = silu_f(a0 * 0.35355339059327373f) * cst;  // 1/sqrt(8)
        hb[wid][0][o0 + 1] = silu_f(a1 * 0.35355339059327373f) * cst;
    }
    __syncwarp();
    // ---- layer 2: 64 -> 64 ----
    {
        float a0 = 0.f, a1 = 0.f;
#pragma unroll 8
        for (int j = 0; j < 64; j++) {
            float hv = hb[wid][0][j];
            float2 wv = *reinterpret_cast<const float2*>(Wr1 + j * 64 + o0);
            a0 = fmaf(hv, wv.x, a0);
            a1 = fmaf(hv, wv.y, a1);
        }
        hb[wid][1][o0]     = silu_f(a0 * 0.125f) * cst;
        hb[wid][1][o0 + 1] = silu_f(a1 * 0.125f) * cst;
    }
    __syncwarp();
    // ---- layer 3: 64 -> 64 (writes back into buf0) ----
    {
        float a0 = 0.f, a1 = 0.f;
#pragma unroll 8
        for (int j = 0; j < 64; j++) {
            float hv = hb[wid][1][j];
            float2 wv = *reinterpret_cast<const float2*>(Wr2 + j * 64 + o0);
            a0 = fmaf(hv, wv.x, a0);
            a1 = fmaf(hv, wv.y, a1);
        }
        hb[wid][0][o0]     = silu_f(a0 * 0.125f) * cst;
        hb[wid][0][o0 + 1] = silu_f(a1 * 0.125f) * cst;
    }
    __syncwarp();
    // ---- layer 4: 64 -> 352 (float4 chunks; lane owns chunks lane, lane+32, lane+64) ----
    {
        float4 acc0 = make_float4(0,0,0,0), acc1 = acc0, acc2 = acc0;
        const float4* W3 = reinterpret_cast<const float4*>(Wr3);  // row stride 88 float4
#pragma unroll 4
        for (int j = 0; j < 64; j++) {
            float hv = hb[wid][0][j];
            const float4* r = W3 + j * 88;
            float4 w0 = __ldg(r + lane);
            acc0.x = fmaf(hv, w0.x, acc0.x); acc0.y = fmaf(hv, w0.y, acc0.y);
            acc0.z = fmaf(hv, w0.z, acc0.z); acc0.w = fmaf(hv, w0.w, acc0.w);
            float4 w1 = __ldg(r + lane + 32);
            acc1.x = fmaf(hv, w1.x, acc1.x); acc1.y = fmaf(hv, w1.y, acc1.y);
            acc1.z = fmaf(hv, w1.z, acc1.z); acc1.w = fmaf(hv, w1.w, acc1.w);
            if (lane < 24) {
                float4 w2 = __ldg(r + lane + 64);
                acc2.x = fmaf(hv, w2.x, acc2.x); acc2.y = fmaf(hv, w2.y, acc2.y);
                acc2.z = fmaf(hv, w2.z, acc2.z); acc2.w = fmaf(hv, w2.w, acc2.w);
            }
        }
        float4* wsf4 = reinterpret_cast<float4*>(ws[wid]);
        acc0.x *= 0.125f; acc0.y *= 0.125f; acc0.z *= 0.125f; acc0.w *= 0.125f;
        acc1.x *= 0.125f; acc1.y *= 0.125f; acc1.z *= 0.125f; acc1.w *= 0.125f;
        wsf4[lane]      = acc0;
        wsf4[lane + 32] = acc1;
        if (lane < 24) {
            acc2.x *= 0.125f; acc2.y *= 0.125f; acc2.z *= 0.125f; acc2.w *= 0.125f;
            wsf4[lane + 64] = acc2;
        }
    }
    __syncwarp();

    // ---- spherical harmonics ----
    const float s1x = 1.7320508075688772f * ux;
    const float s1y = 1.7320508075688772f * uy;
    const float s1z = 1.7320508075688772f * uz;
    const float s20 = 3.872983346207417f * ux * uz;
    const float s21 = 3.872983346207417f * ux * uy;
    const float s22 = 2.23606797749979f * (uy*uy - 0.5f*(ux*ux + uz*uz));
    const float s23 = 3.872983346207417f * uy * uz;
    const float s24 = 1.9364916731037085f * (uz*uz - ux*ux);

    // ---- lane = u channel; load up-projected source features ----
    const float* xp = g_xs + src * 288;
    const float x0  = __ldg(xp + lane);
    const float x10 = __ldg(xp + 32 + lane*3 + 0);
    const float x11 = __ldg(xp + 32 + lane*3 + 1);
    const float x12 = __ldg(xp + 32 + lane*3 + 2);
    const float x20 = __ldg(xp + 128 + lane*5 + 0);
    const float x21 = __ldg(xp + 128 + lane*5 + 1);
    const float x22 = __ldg(xp + 128 + lane*5 + 2);
    const float x23 = __ldg(xp + 128 + lane*5 + 3);
    const float x24 = __ldg(xp + 128 + lane*5 + 4);

    float* mb = g_mid + dst * 1120;

    const float A_ = 0.31622776601683794f;  // 1/sqrt(10)
    const float B_ = 0.18257418583505536f;  // 1/sqrt(30)
    const float AL = 0.11952286093343936f;  // 1/sqrt(70)
    const float BE = 0.20701966780270626f;  // sqrt(3/70)
    const float SQ3 = 1.7320508075688772f;
    const float SQ5 = 2.23606797749979f;

    // path 0: (0,0,0)
    {
        float w = ws[wid][lane];
        atomicAdd(mb + lane, x0 * w);
    }
    // path 1: (1,1,0)
    {
        float w = ws[wid][32 + lane];
        float dot = x10*s1x + x11*s1y + x12*s1z;
        atomicAdd(mb + 32 + lane, 0.5773502691896258f * dot * w);
    }
    // path 2: (2,2,0)
    {
        float w = ws[wid][64 + lane];
        float dot = x20*s20 + x21*s21 + x22*s22 + x23*s23 + x24*s24;
        atomicAdd(mb + 64 + lane, 0.4472135954999579f * dot * w);
    }
    // path 3: (0,1,1)  m[k] = x0 * sh1[k] * w
    {
        float w = ws[wid][96 + lane];
        float c = x0 * w;
        atomicAdd(mb + 96 + lane*3 + 0, c * s1x);
        atomicAdd(mb + 96 + lane*3 + 1, c * s1y);
        atomicAdd(mb + 96 + lane*3 + 2, c * s1z);
    }
    // path 4: (1,0,1)  m[k] = x1[k] * w
    {
        float w = ws[wid][128 + lane];
        atomicAdd(mb + 192 + lane*3 + 0, x10 * w);
        atomicAdd(mb + 192 + lane*3 + 1, x11 * w);
        atomicAdd(mb + 192 + lane*3 + 2, x12 * w);
    }
    // path 5: (1,2,1)  m[k] = sqrt(3)*w * sum_i x1[i] B5[i][k], B5 symmetric
    {
        float w = SQ3 * ws[wid][160 + lane];
        float B00 = -B_*s22 - A_*s24;
        float B01 =  A_*s21;
        float B02 =  A_*s20;
        float B11 =  2.f*B_*s22;
        float B12 =  A_*s23;
        float B22 = -B_*s22 + A_*s24;
        atomicAdd(mb + 288 + lane*3 + 0, w * (x10*B00 + x11*B01 + x12*B02));
        atomicAdd(mb + 288 + lane*3 + 1, w * (x10*B01 + x11*B11 + x12*B12));
        atomicAdd(mb + 288 + lane*3 + 2, w * (x10*B02 + x11*B12 + x12*B22));
    }
    // path 6: (2,1,1)  m[k] = sqrt(3)*w * sum_{i in 5} x2[i] B6[i][k]
    {
        float w = SQ3 * ws[wid][192 + lane];
        float m0 = A_*(x20*s1z + x21*s1y) - B_*x22*s1x - A_*x24*s1x;
        float m1 = A_*(x21*s1x + x23*s1z) + 2.f*B_*x22*s1y;
        float m2 = A_*(x20*s1x + x23*s1y + x24*s1z) - B_*x22*s1z;
        atomicAdd(mb + 384 + lane*3 + 0, w * m0);
        atomicAdd(mb + 384 + lane*3 + 1, w * m1);
        atomicAdd(mb + 384 + lane*3 + 2, w * m2);
    }
    // path 7: (0,2,2)  m[k] = x0 * sh2[k] * w
    {
        float w = ws[wid][224 + lane];
        float c = x0 * w;
        atomicAdd(mb + 480 + lane*5 + 0, c * s20);
        atomicAdd(mb + 480 + lane*5 + 1, c * s21);
        atomicAdd(mb + 480 + lane*5 + 2, c * s22);
        atomicAdd(mb + 480 + lane*5 + 3, c * s23);
        atomicAdd(mb + 480 + lane*5 + 4, c * s24);
    }
    // path 8: (1,1,2)  m[k] = sqrt(5)*w * sum_{i in 3} x1[i] B8[i][k]
    {
        float w = SQ5 * ws[wid][256 + lane];
        float m0 = A_*(x10*s1z + x12*s1x);
        float m1 = A_*(x10*s1y + x11*s1x);
        float m2 = B_*(-x10*s1x + 2.f*x11*s1y - x12*s1z);
        float m3 = A_*(x11*s1z + x12*s1y);
        float m4 = A_*(-x10*s1x + x12*s1z);
        atomicAdd(mb + 640 + lane*5 + 0, w * m0);
        atomicAdd(mb + 640 + lane*5 + 1, w * m1);
        atomicAdd(mb + 640 + lane*5 + 2, w * m2);
        atomicAdd(mb + 640 + lane*5 + 3, w * m3);
        atomicAdd(mb + 640 + lane*5 + 4, w * m4);
    }
    // path 9: (2,0,2)  m[k] = x2[k] * w
    {
        float w = ws[wid][288 + lane];
        atomicAdd(mb + 800 + lane*5 + 0, x20 * w);
        atomicAdd(mb + 800 + lane*5 + 1, x21 * w);
        atomicAdd(mb + 800 + lane*5 + 2, x22 * w);
        atomicAdd(mb + 800 + lane*5 + 3, x23 * w);
        atomicAdd(mb + 800 + lane*5 + 4, x24 * w);
    }
    // path 10: (2,2,2)  m[k] = sqrt(5)*w * sum_i x2[i] B10[i][k], B10 symmetric
    {
        float w = SQ5 * ws[wid][320 + lane];
        float m0 = x20*(2.f*AL*s22) + x21*(-BE*s23) + x22*(2.f*AL*s20) + x23*(-BE*s21);
        float m1 = x20*(-BE*s23) + x21*(-AL*s22 + BE*s24) + x22*(-AL*s21) + x23*(-BE*s20) + x24*(BE*s21);
        float m2 = x20*(2.f*AL*s20) + x21*(-AL*s21) + x22*(-2.f*AL*s22) + x23*(-AL*s23) + x24*(2.f*AL*s24);
        float m3 = x20*(-BE*s21) + x21*(-BE*s20) + x22*(-AL*s23) + x23*(-AL*s22 - BE*s24) + x24*(-BE*s23);
        float m4 = x21*(BE*s21) + x22*(2.f*AL*s24) + x23*(-BE*s23) + x24*(2.f*AL*s22);
        atomicAdd(mb + 960 + lane*5 + 0, w * m0);
        atomicAdd(mb + 960 + lane*5 + 1, w * m1);
        atomicAdd(mb + 960 + lane*5 + 2, w * m2);
        atomicAdd(mb + 960 + lane*5 + 3, w * m3);
        atomicAdd(mb + 960 + lane*5 + 4, w * m4);
    }
}

// ---------------- per-node output projection --------------------------------
__global__ void out_kernel(const float* __restrict__ Wo0,
                           const float* __restrict__ Wo1,
                           const float* __restrict__ Wo2,
                           float* __restrict__ out) {
    const int n = blockIdx.x;
    const int t = threadIdx.x;  // 288 threads
    __shared__ float ms[1120];
    for (int j = t; j < 1120; j += 288) ms[j] = g_mid[n * 1120 + j];
    __syncthreads();

    float acc = 0.f;
    if (t < 32) {
#pragma unroll 8
        for (int u = 0; u < 96; u++)
            acc = fmaf(ms[u], __ldg(Wo0 + u * 32 + t), acc);
        acc *= 0.006378879538497859f;   // 1/(sqrt(96)*16)
    } else if (t < 128) {
        int c = t - 32, w = c / 3, i = c % 3;
#pragma unroll 8
        for (int u = 0; u < 128; u++)
            acc = fmaf(ms[96 + u * 3 + i], __ldg(Wo1 + u * 32 + w), acc);
        acc *= 0.005524271728019903f;   // 1/(sqrt(128)*16)
    } else {
        int c = t - 128, w = c / 5, i = c % 5;
#pragma unroll 8
        for (int u = 0; u < 128; u++)
            acc = fmaf(ms[480 + u * 5 + i], __ldg(Wo2 + u * 32 + w), acc);
        acc *= 0.005524271728019903f;
    }
    out[n * 288 + t] = acc;
}

// ---------------- launch -----------------------------------------------------
extern "C" void kernel_launch(void* const* d_in, const int* in_sizes, int n_in,
                              void* d_out, int out_size) {
    const float* f_in   = (const float*)d_in[0];
    const float* pos    = (const float*)d_in[1];
    const int*   batch  = (const int*)d_in[2];
    const int*   esrc   = (const int*)d_in[3];
    const int*   edst   = (const int*)d_in[4];
    const float* shifts = (const float*)d_in[5];
    const float* cell   = (const float*)d_in[6];
    // last 10 inputs are always the weights, whether num_nodes is materialized or not
    const int wb = n_in - 10;
    const float* Wu0 = (const float*)d_in[wb + 0];
    const float* Wu1 = (const float*)d_in[wb + 1];
    const float* Wu2 = (const float*)d_in[wb + 2];
    const float* Wr0 = (const float*)d_in[wb + 3];
    const float* Wr1 = (const float*)d_in[wb + 4];
    const float* Wr2 = (const float*)d_in[wb + 5];
    const float* Wr3 = (const float*)d_in[wb + 6];
    const float* Wo0 = (const float*)d_in[wb + 7];
    const float* Wo1 = (const float*)d_in[wb + 8];
    const float* Wo2 = (const float*)d_in[wb + 9];

    const int N = in_sizes[0] / 288;
    const int E = in_sizes[3];

    cst_kernel<<<1, 256>>>();
    const int n4 = N * 1120 / 4;
    zero_kernel<<<(n4 + 255) / 256, 256>>>(n4);
    up_kernel<<<N, 288>>>(f_in, Wu0, Wu1, Wu2);
    edge_kernel<<<(E + 7) / 8, 256>>>(pos, batch, esrc, edst, shifts, cell,
                                      Wr0, Wr1, Wr2, Wr3, E);
    out_kernel<<<N, 288>>>(Wo0, Wo1, Wo2, (float*)d_out);
}

// round 4
// speedup vs baseline: 1.6221x; 1.6221x over previous
#include <cuda_runtime.h>
#include <math.h>

#define MAXN 10000

// ---------------- device scratch --------------------------------------------
__device__ float  g_cst;                       // CST_SILU
__device__ float4 g_xs4[MAXN * 96];            // up-projected node features, [node][u][12f] (pad 9..11)
__device__ float4 g_mid4[MAXN * 288];          // aggregated messages, 1152 f/node

// g_mid per-node layout (1152 floats):
//   [0:128)    l0: u*4 + s   (s=0..2 paths (0,0,0),(1,1,0),(2,2,0); s=3 pad)
//   [128:512)  l1: 128 + u*12 + s*3 + i   (s=0..3 paths (0,1,1),(1,0,1),(1,2,1),(2,1,1))
//   [512:1152) l2: 512 + u*20 + s*5 + k   (s=0..3 paths (0,2,2),(1,1,2),(2,0,2),(2,2,2))
// g_xs per-node layout (384 floats): u*12 + {x0, x1[0..2], x2[0..4], pad*3}

__device__ __forceinline__ float silu_f(float v) {
    return __fdividef(v, 1.0f + __expf(-v));
}

// ---------------- CST_SILU via composite Simpson (double) -------------------
__global__ void cst_kernel() {
    __shared__ double red[256];
    const int t = threadIdx.x;
    const int NI = 4096;
    const double h = 24.0 / NI;
    double s = 0.0;
    for (int i = t; i <= NI; i += 256) {
        double xx = -12.0 + h * i;
        double sig = 1.0 / (1.0 + exp(-xx));
        double f = xx * sig;
        f = f * f * exp(-0.5 * xx * xx);
        double c = (i == 0 || i == NI) ? 1.0 : ((i & 1) ? 4.0 : 2.0);
        s += c * f;
    }
    red[t] = s;
    __syncthreads();
    for (int o = 128; o > 0; o >>= 1) {
        if (t < o) red[t] += red[t + o];
        __syncthreads();
    }
    if (t == 0) {
        double I = red[0] * h / 3.0 / 2.5066282746310005024;
        g_cst = (float)(1.0 / sqrt(I));
    }
}

// ---------------- zero mid ---------------------------------------------------
__global__ void zero_kernel(int n4) {
    int i = blockIdx.x * blockDim.x + threadIdx.x;
    if (i < n4) g_mid4[i] = make_float4(0.f, 0.f, 0.f, 0.f);
}

// ---------------- node up-projection ----------------------------------------
__global__ void up_kernel(const float* __restrict__ f_in,
                          const float* __restrict__ Wu0,
                          const float* __restrict__ Wu1,
                          const float* __restrict__ Wu2) {
    const int n = blockIdx.x;
    const int t = threadIdx.x;  // 288
    __shared__ float fs[288];
    fs[t] = f_in[n * 288 + t];
    __syncthreads();
    int i, off, w, d, slot;
    const float* W;
    if (t < 32)       { w = t;         i = 0;         d = 1; off = 0;   W = Wu0; slot = 0; }
    else if (t < 128) { int c = t-32;  w = c/3; i = c%3; d = 3; off = 32;  W = Wu1; slot = 1 + i; }
    else              { int c = t-128; w = c/5; i = c%5; d = 5; off = 128; W = Wu2; slot = 4 + i; }
    float acc = 0.f;
#pragma unroll 8
    for (int u = 0; u < 32; u++)
        acc = fmaf(fs[off + u * d + i], __ldg(W + u * 32 + w), acc);
    reinterpret_cast<float*>(g_xs4)[n * 384 + w * 12 + slot] = acc * 0.17677669529663687f;
}

// ---------------- radial MLP 64->64 layer (4 edges per warp) ----------------
__device__ __forceinline__ void mlp64(const float* __restrict__ in,
                                      float* __restrict__ out,
                                      const float* __restrict__ W,
                                      int o0, float cst) {
    float a0[4] = {0,0,0,0}, a1[4] = {0,0,0,0};
#pragma unroll 2
    for (int j4 = 0; j4 < 16; j4++) {
        float h0[4], h1[4], h2[4], h3[4];
#pragma unroll
        for (int e = 0; e < 4; e++) {
            float4 v = *reinterpret_cast<const float4*>(in + e * 64 + j4 * 4);
            h0[e] = v.x; h1[e] = v.y; h2[e] = v.z; h3[e] = v.w;
        }
#pragma unroll
        for (int jj = 0; jj < 4; jj++) {
            float2 wv = *reinterpret_cast<const float2*>(W + (j4 * 4 + jj) * 64 + o0);
#pragma unroll
            for (int e = 0; e < 4; e++) {
                float hv = (jj == 0) ? h0[e] : (jj == 1) ? h1[e] : (jj == 2) ? h2[e] : h3[e];
                a0[e] = fmaf(hv, wv.x, a0[e]);
                a1[e] = fmaf(hv, wv.y, a1[e]);
            }
        }
    }
#pragma unroll
    for (int e = 0; e < 4; e++) {
        *reinterpret_cast<float2*>(out + e * 64 + o0) =
            make_float2(silu_f(a0[e] * 0.125f) * cst, silu_f(a1[e] * 0.125f) * cst);
    }
}

// ---------------- fused per-edge kernel (warp handles 4 edges) --------------
__global__ void __launch_bounds__(256) edge_kernel(
    const float* __restrict__ pos, const int* __restrict__ batch,
    const int* __restrict__ esrc, const int* __restrict__ edst,
    const float* __restrict__ shifts, const float* __restrict__ cell,
    const float* __restrict__ Wr0, const float* __restrict__ Wr1,
    const float* __restrict__ Wr2, const float* __restrict__ Wr3, int E)
{
    extern __shared__ float sm[];
    const int wid  = threadIdx.x >> 5;
    const int lane = threadIdx.x & 31;
    float* hA  = sm + (wid * 4) * 64;                 // [4][64]
    float* hB  = sm + 2048 + (wid * 4) * 64;          // [4][64]
    float* wsm = sm + 4096 + (wid * 4) * 352;         // [4][352]

    const int base = (blockIdx.x * 8 + wid) * 4;
    const float cst = g_cst;

    float uxr[4], uyr[4], uzr[4], Lr[4];
#pragma unroll
    for (int e = 0; e < 4; e++) {
        int ei = (base + e < E) ? base + e : E - 1;
        const int src = __ldg(esrc + ei);
        const int dst = __ldg(edst + ei);
        const float sx = __ldg(shifts + 3*ei), sy = __ldg(shifts + 3*ei+1), sz = __ldg(shifts + 3*ei+2);
        const float* Cc = cell + 9 * __ldg(batch + src);
        float vx = __ldg(pos+3*dst+0) - __ldg(pos+3*src+0) + sx*__ldg(Cc+0) + sy*__ldg(Cc+3) + sz*__ldg(Cc+6);
        float vy = __ldg(pos+3*dst+1) - __ldg(pos+3*src+1) + sx*__ldg(Cc+1) + sy*__ldg(Cc+4) + sz*__ldg(Cc+7);
        float vz = __ldg(pos+3*dst+2) - __ldg(pos+3*src+2) + sx*__ldg(Cc+2) + sy*__ldg(Cc+5) + sz*__ldg(Cc+8);
        float L = sqrtf(vx*vx + vy*vy + vz*vz);
        float inv = 1.0f / fmaxf(L, 1e-12f);
        uxr[e] = vx*inv; uyr[e] = vy*inv; uzr[e] = vz*inv; Lr[e] = L;
    }

    // ---- radial embedding, cooperative: one expf per lane ----
    {
        const int k = lane & 7;
        float Ls = (lane < 8) ? Lr[0] : (lane < 16) ? Lr[1] : (lane < 24) ? Lr[2] : Lr[3];
        float tt = (Ls - (float)(k + 1) * (5.0f / 9.0f)) * 1.8f;
        hB[(lane >> 3) * 64 + k] = __expf(-tt * tt) * 2.525381361380527f;  // sqrt(8)/1.12
    }
    __syncwarp();

    const int o0 = lane * 2;
    // ---- layer 1: 8 -> 64 (hB -> hA) ----
    {
        float a0[4] = {0,0,0,0}, a1[4] = {0,0,0,0};
#pragma unroll
        for (int j = 0; j < 8; j++) {
            float2 wv = *reinterpret_cast<const float2*>(Wr0 + j * 64 + o0);
#pragma unroll
            for (int e = 0; e < 4; e++) {
                float hv = hB[e * 64 + j];
                a0[e] = fmaf(hv, wv.x, a0[e]);
                a1[e] = fmaf(hv, wv.y, a1[e]);
            }
        }
#pragma unroll
        for (int e = 0; e < 4; e++) {
            *reinterpret_cast<float2*>(hA + e * 64 + o0) =
                make_float2(silu_f(a0[e] * 0.35355339059327373f) * cst,
                            silu_f(a1[e] * 0.35355339059327373f) * cst);
        }
    }
    __syncwarp();
    mlp64(hA, hB, Wr1, o0, cst);   // layer 2
    __syncwarp();
    mlp64(hB, hA, Wr2, o0, cst);   // layer 3
    __syncwarp();

    // ---- layer 4: 64 -> 352 (hA -> wsm), weights amortized over 4 edges ----
    {
        float4 acc0[4], acc1[4], acc2[4];
#pragma unroll
        for (int e = 0; e < 4; e++) {
            acc0[e] = make_float4(0,0,0,0); acc1[e] = acc0[e]; acc2[e] = acc0[e];
        }
        const float4* W3 = reinterpret_cast<const float4*>(Wr3);  // row stride 88 float4
#pragma unroll 1
        for (int j4 = 0; j4 < 16; j4++) {
            float h0[4], h1[4], h2[4], h3[4];
#pragma unroll
            for (int e = 0; e < 4; e++) {
                float4 v = *reinterpret_cast<const float4*>(hA + e * 64 + j4 * 4);
                h0[e] = v.x; h1[e] = v.y; h2[e] = v.z; h3[e] = v.w;
            }
#pragma unroll
            for (int jj = 0; jj < 4; jj++) {
                const float4* r = W3 + (j4 * 4 + jj) * 88;
                float4 w0 = __ldg(r + lane);
                float4 w1 = __ldg(r + lane + 32);
                float4 w2;
                if (lane < 24) w2 = __ldg(r + lane + 64);
#pragma unroll
                for (int e = 0; e < 4; e++) {
                    float hv = (jj == 0) ? h0[e] : (jj == 1) ? h1[e] : (jj == 2) ? h2[e] : h3[e];
                    acc0[e].x = fmaf(hv, w0.x, acc0[e].x); acc0[e].y = fmaf(hv, w0.y, acc0[e].y);
                    acc0[e].z = fmaf(hv, w0.z, acc0[e].z); acc0[e].w = fmaf(hv, w0.w, acc0[e].w);
                    acc1[e].x = fmaf(hv, w1.x, acc1[e].x); acc1[e].y = fmaf(hv, w1.y, acc1[e].y);
                    acc1[e].z = fmaf(hv, w1.z, acc1[e].z); acc1[e].w = fmaf(hv, w1.w, acc1[e].w);
                    if (lane < 24) {
                        acc2[e].x = fmaf(hv, w2.x, acc2[e].x); acc2[e].y = fmaf(hv, w2.y, acc2[e].y);
                        acc2[e].z = fmaf(hv, w2.z, acc2[e].z); acc2[e].w = fmaf(hv, w2.w, acc2[e].w);
                    }
                }
            }
        }
#pragma unroll
        for (int e = 0; e < 4; e++) {
            float4* wsf4 = reinterpret_cast<float4*>(wsm + e * 352);
            float4 a = acc0[e]; a.x *= 0.125f; a.y *= 0.125f; a.z *= 0.125f; a.w *= 0.125f;
            wsf4[lane] = a;
            a = acc1[e]; a.x *= 0.125f; a.y *= 0.125f; a.z *= 0.125f; a.w *= 0.125f;
            wsf4[lane + 32] = a;
            if (lane < 24) {
                a = acc2[e]; a.x *= 0.125f; a.y *= 0.125f; a.z *= 0.125f; a.w *= 0.125f;
                wsf4[lane + 64] = a;
            }
        }
    }
    __syncwarp();

    // ---- tensor product + vector atomics, per edge ----
    const float A_  = 0.31622776601683794f;  // 1/sqrt(10)
    const float B_  = 0.18257418583505536f;  // 1/sqrt(30)
    const float AL  = 0.11952286093343936f;  // 1/sqrt(70)
    const float BE  = 0.20701966780270626f;  // sqrt(3/70)
    const float SQ3 = 1.7320508075688772f;
    const float SQ5 = 2.23606797749979f;

#pragma unroll
    for (int e = 0; e < 4; e++) {
        if (base + e >= E) break;
        const int src = __ldg(esrc + base + e);
        const int dst = __ldg(edst + base + e);

        const float ux = uxr[e], uy = uyr[e], uz = uzr[e];
        const float s1x = SQ3 * ux, s1y = SQ3 * uy, s1z = SQ3 * uz;
        const float s20 = 3.872983346207417f * ux * uz;
        const float s21 = 3.872983346207417f * ux * uy;
        const float s22 = SQ5 * (uy*uy - 0.5f*(ux*ux + uz*uz));
        const float s23 = 3.872983346207417f * uy * uz;
        const float s24 = 1.9364916731037085f * (uz*uz - ux*ux);

        // radial weights for this lane's u channel
        float w[11];
#pragma unroll
        for (int k = 0; k < 11; k++) w[k] = wsm[e * 352 + k * 32 + lane];

        // source features (vectorized)
        const float4* xp = g_xs4 + src * 96 + lane * 3;
        const float4 xa = __ldg(xp);        // x0, x10, x11, x12
        const float4 xb = __ldg(xp + 1);    // x20, x21, x22, x23
        const float4 xc = __ldg(xp + 2);    // x24, pad...
        const float x0 = xa.x;
        const float x10 = xa.y, x11 = xa.z, x12 = xa.w;
        const float x20 = xb.x, x21 = xb.y, x22 = xb.z, x23 = xb.w, x24 = xc.x;

        // l0 outputs
        const float p0 = x0 * w[0];
        const float p1 = 0.5773502691896258f * (x10*s1x + x11*s1y + x12*s1z) * w[1];
        const float p2 = 0.4472135954999579f * (x20*s20 + x21*s21 + x22*s22 + x23*s23 + x24*s24) * w[2];

        // l1 outputs
        const float c3 = x0 * w[3];
        const float p3x = c3 * s1x, p3y = c3 * s1y, p3z = c3 * s1z;
        const float p4x = x10 * w[4], p4y = x11 * w[4], p4z = x12 * w[4];
        float p5x, p5y, p5z;
        {
            float wv = SQ3 * w[5];
            float B00 = -B_*s22 - A_*s24;
            float B01 =  A_*s21;
            float B02 =  A_*s20;
            float B11 =  2.f*B_*s22;
            float B12 =  A_*s23;
            float B22 = -B_*s22 + A_*s24;
            p5x = wv * (x10*B00 + x11*B01 + x12*B02);
            p5y = wv * (x10*B01 + x11*B11 + x12*B12);
            p5z = wv * (x10*B02 + x11*B12 + x12*B22);
        }
        float p6x, p6y, p6z;
        {
            float wv = SQ3 * w[6];
            p6x = wv * (A_*(x20*s1z + x21*s1y) - B_*x22*s1x - A_*x24*s1x);
            p6y = wv * (A_*(x21*s1x + x23*s1z) + 2.f*B_*x22*s1y);
            p6z = wv * (A_*(x20*s1x + x23*s1y + x24*s1z) - B_*x22*s1z);
        }

        // l2 outputs
        const float c7 = x0 * w[7];
        const float p70 = c7*s20, p71 = c7*s21, p72 = c7*s22, p73 = c7*s23, p74 = c7*s24;
        float p80, p81, p82, p83, p84;
        {
            float wv = SQ5 * w[8];
            p80 = wv * (A_*(x10*s1z + x12*s1x));
            p81 = wv * (A_*(x10*s1y + x11*s1x));
            p82 = wv * (B_*(-x10*s1x + 2.f*x11*s1y - x12*s1z));
            p83 = wv * (A_*(x11*s1z + x12*s1y));
            p84 = wv * (A_*(-x10*s1x + x12*s1z));
        }
        const float p90 = x20*w[9], p91 = x21*w[9], p92 = x22*w[9], p93 = x23*w[9], p94 = x24*w[9];
        float pa0, pa1, pa2, pa3, pa4;
        {
            float wv = SQ5 * w[10];
            pa0 = wv * (x20*(2.f*AL*s22) + x21*(-BE*s23) + x22*(2.f*AL*s20) + x23*(-BE*s21));
            pa1 = wv * (x20*(-BE*s23) + x21*(-AL*s22 + BE*s24) + x22*(-AL*s21) + x23*(-BE*s20) + x24*(BE*s21));
            pa2 = wv * (x20*(2.f*AL*s20) + x21*(-AL*s21) + x22*(-2.f*AL*s22) + x23*(-AL*s23) + x24*(2.f*AL*s24));
            pa3 = wv * (x20*(-BE*s21) + x21*(-BE*s20) + x22*(-AL*s23) + x23*(-AL*s22 - BE*s24) + x24*(-BE*s23));
            pa4 = wv * (x21*(BE*s21) + x22*(2.f*AL*s24) + x23*(-BE*s23) + x24*(2.f*AL*s22));
        }

        float* mb = reinterpret_cast<float*>(g_mid4) + dst * 1152;
        atomicAdd(reinterpret_cast<float4*>(mb + lane * 4), make_float4(p0, p1, p2, 0.f));
        float4* mb1 = reinterpret_cast<float4*>(mb + 128 + lane * 12);
        atomicAdd(mb1 + 0, make_float4(p3x, p3y, p3z, p4x));
        atomicAdd(mb1 + 1, make_float4(p4y, p4z, p5x, p5y));
        atomicAdd(mb1 + 2, make_float4(p5z, p6x, p6y, p6z));
        float4* mb2 = reinterpret_cast<float4*>(mb + 512 + lane * 20);
        atomicAdd(mb2 + 0, make_float4(p70, p71, p72, p73));
        atomicAdd(mb2 + 1, make_float4(p74, p80, p81, p82));
        atomicAdd(mb2 + 2, make_float4(p83, p84, p90, p91));
        atomicAdd(mb2 + 3, make_float4(p92, p93, p94, pa0));
        atomicAdd(mb2 + 4, make_float4(pa1, pa2, pa3, pa4));
    }
}

// ---------------- per-node output projection --------------------------------
__global__ void out_kernel(const float* __restrict__ Wo0,
                           const float* __restrict__ Wo1,
                           const float* __restrict__ Wo2,
                           float* __restrict__ out) {
    const int n = blockIdx.x;
    const int t = threadIdx.x;  // 288
    __shared__ float ms[1152];
    reinterpret_cast<float4*>(ms)[t] = g_mid4[n * 288 + t];
    __syncthreads();

    float acc = 0.f;
    if (t < 32) {
#pragma unroll
        for (int s = 0; s < 3; s++)
#pragma unroll 8
            for (int u = 0; u < 32; u++)
                acc = fmaf(ms[u * 4 + s], __ldg(Wo0 + (s * 32 + u) * 32 + t), acc);
        acc *= 0.006378879538497859f;   // 1/(sqrt(96)*16)
    } else if (t < 128) {
        int c = t - 32, w = c / 3, i = c % 3;
#pragma unroll
        for (int s = 0; s < 4; s++)
#pragma unroll 8
            for (int u = 0; u < 32; u++)
                acc = fmaf(ms[128 + u * 12 + s * 3 + i], __ldg(Wo1 + (s * 32 + u) * 32 + w), acc);
        acc *= 0.005524271728019903f;   // 1/(sqrt(128)*16)
    } else {
        int c = t - 128, w = c / 5, i = c % 5;
#pragma unroll
        for (int s = 0; s < 4; s++)
#pragma unroll 8
            for (int u = 0; u < 32; u++)
                acc = fmaf(ms[512 + u * 20 + s * 5 + i], __ldg(Wo2 + (s * 32 + u) * 32 + w), acc);
        acc *= 0.005524271728019903f;
    }
    out[n * 288 + t] = acc;
}

// ---------------- launch -----------------------------------------------------
extern "C" void kernel_launch(void* const* d_in, const int* in_sizes, int n_in,
                              void* d_out, int out_size) {
    const float* f_in   = (const float*)d_in[0];
    const float* pos    = (const float*)d_in[1];
    const int*   batch  = (const int*)d_in[2];
    const int*   esrc   = (const int*)d_in[3];
    const int*   edst   = (const int*)d_in[4];
    const float* shifts = (const float*)d_in[5];
    const float* cell   = (const float*)d_in[6];
    const int wb = n_in - 10;
    const float* Wu0 = (const float*)d_in[wb + 0];
    const float* Wu1 = (const float*)d_in[wb + 1];
    const float* Wu2 = (const float*)d_in[wb + 2];
    const float* Wr0 = (const float*)d_in[wb + 3];
    const float* Wr1 = (const float*)d_in[wb + 4];
    const float* Wr2 = (const float*)d_in[wb + 5];
    const float* Wr3 = (const float*)d_in[wb + 6];
    const float* Wo0 = (const float*)d_in[wb + 7];
    const float* Wo1 = (const float*)d_in[wb + 8];
    const float* Wo2 = (const float*)d_in[wb + 9];

    const int N = in_sizes[0] / 288;
    const int E = in_sizes[3];

    static int smem_set = 0;
    const int smem_bytes = (2048 + 2048 + 8 * 4 * 352) * 4;  // 61440
    if (!smem_set) {
        cudaFuncSetAttribute(edge_kernel, cudaFuncAttributeMaxDynamicSharedMemorySize, smem_bytes);
        smem_set = 1;
    }

    cst_kernel<<<1, 256>>>();
    const int n4 = N * 288;
    zero_kernel<<<(n4 + 255) / 256, 256>>>(n4);
    up_kernel<<<N, 288>>>(f_in, Wu0, Wu1, Wu2);
    edge_kernel<<<(E + 31) / 32, 256, smem_bytes>>>(pos, batch, esrc, edst, shifts, cell,
                                                    Wr0, Wr1, Wr2, Wr3, E);
    out_kernel<<<N, 288>>>(Wo0, Wo1, Wo2, (float*)d_out);
}